// round 14
// baseline (speedup 1.0000x reference)
#include <cuda_runtime.h>
#include <cuda_fp16.h>
#include <math.h>
#include <stdint.h>

#define TT   2048
#define DD   1024
#define HH   16
#define DH   64
#define DFF  4096
#define NQKV 3072

// ---------------- scratch ----------------
__device__ __half g_h1 [TT * DD];
__device__ __half g_qkv[TT * NQKV];
__device__ __half g_ctx[TT * DD];
__device__ float  g_x2 [TT * DD];
__device__ __half g_h2 [TT * DD];
__device__ __half g_ffn[TT * DFF];
__device__ float  g_part[2 * TT * DD];
__device__ __half g_wt [12 * 1024 * 1024];  // transposed fp16 weights

__device__ __forceinline__ float ex2_fast(float x) {
    float y;
    asm("ex2.approx.ftz.f32 %0, %1;" : "=f"(y) : "f"(x));
    return y;
}

__device__ __forceinline__ float gelu_f(float v) {
    return 0.5f * v * (1.0f + erff(v * 0.70710678118654752f));
}

__device__ __forceinline__ void mma_f16(float* c, const uint32_t* a, const uint32_t* b) {
    asm volatile(
        "mma.sync.aligned.m16n8k16.row.col.f32.f16.f16.f32 "
        "{%0,%1,%2,%3}, {%4,%5,%6,%7}, {%8,%9}, {%0,%1,%2,%3};"
        : "+f"(c[0]), "+f"(c[1]), "+f"(c[2]), "+f"(c[3])
        : "r"(a[0]), "r"(a[1]), "r"(a[2]), "r"(a[3]), "r"(b[0]), "r"(b[1]));
}

__device__ __forceinline__ void ldsm_x4(uint32_t& r0, uint32_t& r1, uint32_t& r2, uint32_t& r3,
                                        uint32_t addr) {
    asm volatile("ldmatrix.sync.aligned.m8n8.x4.shared.b16 {%0,%1,%2,%3}, [%4];"
                 : "=r"(r0), "=r"(r1), "=r"(r2), "=r"(r3) : "r"(addr));
}

__device__ __forceinline__ uint32_t smem_u32(const void* p) {
    uint32_t a;
    asm("{ .reg .u64 t; cvta.to.shared.u64 t, %1; cvt.u32.u64 %0, t; }" : "=r"(a) : "l"(p));
    return a;
}

__device__ __forceinline__ void cp_async16(uint32_t saddr, const void* gptr) {
    asm volatile("cp.async.cg.shared.global [%0], [%1], 16;" :: "r"(saddr), "l"(gptr) : "memory");
}
#define CP_COMMIT() asm volatile("cp.async.commit_group;" ::: "memory")
#define CP_WAIT0()  asm volatile("cp.async.wait_group 0;" ::: "memory")
#define CP_WAIT1()  asm volatile("cp.async.wait_group 1;" ::: "memory")
#define CP_WAIT2()  asm volatile("cp.async.wait_group 2;" ::: "memory")

// ---------------- weight transpose + RNE fp16 convert (once per launch) ----------------
__global__ void wtrans_kernel(const float* __restrict__ wq, const float* __restrict__ wk,
                              const float* __restrict__ wv, const float* __restrict__ wo,
                              const float* __restrict__ w1, const float* __restrict__ w2,
                              __half* __restrict__ dst) {
    __shared__ float tile[32][33];
    int t = blockIdx.x;
    const int T0 = 96 * 32, T1 = 32 * 32, T2 = 128 * 32;
    int nt, kt, Kd, Nfull, mode;
    const float* s1 = nullptr;
    __half* d;
    if (t < T0)                { mode = 0; nt = t / 32;  kt = t % 32;  d = dst;                 Kd = 1024; Nfull = 0; }
    else if (t < T0 + T1)      { t -= T0;       mode = 1; nt = t / 32;  kt = t % 32;  d = dst + 3 * 1024 * 1024; Kd = 1024; Nfull = 1024; s1 = wo; }
    else if (t < T0 + T1 + T2) { t -= T0 + T1;  mode = 2; nt = t / 32;  kt = t % 32;  d = dst + 4 * 1024 * 1024; Kd = 1024; Nfull = 4096; s1 = w1; }
    else                       { t -= T0 + T1 + T2; mode = 3; nt = t / 128; kt = t % 128; d = dst + 8 * 1024 * 1024; Kd = 4096; Nfull = 1024; s1 = w2; }

    int tx = threadIdx.x & 31, ty = threadIdx.x >> 5;
    #pragma unroll
    for (int i = 0; i < 4; i++) {
        int r = ty + i * 8;
        int k = kt * 32 + r;
        int n = nt * 32 + tx;
        float val;
        if (mode == 0) {
            int which = n >> 10, head = (n >> 6) & 15, e = n & 63;
            const float* w = (which == 0) ? wq : (which == 1) ? wk : wv;
            val = w[(size_t)head * (DD * DH) + (size_t)k * DH + e];
        } else {
            val = s1[(size_t)k * Nfull + n];
        }
        tile[r][tx] = val;
    }
    __syncthreads();
    #pragma unroll
    for (int i = 0; i < 4; i++) {
        int r = ty + i * 8;
        d[(size_t)(nt * 32 + r) * Kd + kt * 32 + tx] = __float2half_rn(tile[tx][r]);
    }
}

// ---------------- LayerNorm (torch-style; fp16 RNE output) ----------------
__global__ void ln_kernel(const float* __restrict__ x, const float* __restrict__ g,
                          const float* __restrict__ b, __half* __restrict__ out) {
    int row = blockIdx.x;
    const float* xr = x + row * DD;
    float s = 0.f, s2 = 0.f;
    for (int i = threadIdx.x; i < DD; i += 256) { float v = xr[i]; s += v; s2 += v * v; }
    #pragma unroll
    for (int o = 16; o > 0; o >>= 1) {
        s  += __shfl_xor_sync(0xffffffffu, s,  o);
        s2 += __shfl_xor_sync(0xffffffffu, s2, o);
    }
    __shared__ float sm[8], sm2[8], stats[2];
    int w = threadIdx.x >> 5, lane = threadIdx.x & 31;
    if (lane == 0) { sm[w] = s; sm2[w] = s2; }
    __syncthreads();
    if (threadIdx.x == 0) {
        float ts = 0.f, ts2 = 0.f;
        #pragma unroll
        for (int i = 0; i < 8; i++) { ts += sm[i]; ts2 += sm2[i]; }
        float mean = ts / (float)DD;
        float var  = fmaxf((ts2 - (float)DD * mean * mean) / (float)(DD - 1), 0.f);
        stats[0] = mean; stats[1] = 1.f / (sqrtf(var) + 1e-8f);
    }
    __syncthreads();
    float mean = stats[0], rstd = stats[1];
    for (int i = threadIdx.x; i < DD / 2; i += 256) {
        float2 v = reinterpret_cast<const float2*>(xr)[i];
        float o0 = (v.x - mean) * rstd * g[i * 2] + b[i * 2];
        float o1 = (v.y - mean) * rstd * g[i * 2 + 1] + b[i * 2 + 1];
        reinterpret_cast<__half2*>(out + (size_t)row * DD)[i] = __floats2half2_rn(o0, o1);
    }
}

// ---------------- fused split-K reduce + LayerNorm ----------------
__global__ void reduce_ln(const float* __restrict__ part, const float* __restrict__ bias,
                          const float* __restrict__ resid, const float* __restrict__ g,
                          const float* __restrict__ b, float* __restrict__ x2,
                          __half* __restrict__ h2) {
    int row = blockIdx.x, tid = threadIdx.x;
    __shared__ float rowbuf[DD];
    __shared__ float sm1[8], sm2v[8], stats[2];
    const float4* p0 = reinterpret_cast<const float4*>(part) + (size_t)row * (DD / 4);
    const float4* p1 = reinterpret_cast<const float4*>(part) + (TT * DD / 4) + (size_t)row * (DD / 4);
    const float4* rv4 = reinterpret_cast<const float4*>(resid) + (size_t)row * (DD / 4);
    const float4* bv4 = reinterpret_cast<const float4*>(bias);
    float s = 0.f, s2 = 0.f;
    for (int i = tid; i < DD / 4; i += 256) {
        float4 a = p0[i], c = p1[i], bv = bv4[i], r = rv4[i];
        float4 v;
        v.x = a.x + c.x + bv.x + r.x; v.y = a.y + c.y + bv.y + r.y;
        v.z = a.z + c.z + bv.z + r.z; v.w = a.w + c.w + bv.w + r.w;
        reinterpret_cast<float4*>(x2 + (size_t)row * DD)[i] = v;
        *reinterpret_cast<float4*>(rowbuf + i * 4) = v;
        s += v.x + v.y + v.z + v.w;
        s2 += v.x * v.x + v.y * v.y + v.z * v.z + v.w * v.w;
    }
    #pragma unroll
    for (int o = 16; o > 0; o >>= 1) {
        s  += __shfl_xor_sync(0xffffffffu, s,  o);
        s2 += __shfl_xor_sync(0xffffffffu, s2, o);
    }
    int w = tid >> 5, lane = tid & 31;
    if (lane == 0) { sm1[w] = s; sm2v[w] = s2; }
    __syncthreads();
    if (tid == 0) {
        float ts = 0.f, ts2 = 0.f;
        #pragma unroll
        for (int i = 0; i < 8; i++) { ts += sm1[i]; ts2 += sm2v[i]; }
        float mean = ts / (float)DD;
        float var  = fmaxf((ts2 - (float)DD * mean * mean) / (float)(DD - 1), 0.f);
        stats[0] = mean; stats[1] = 1.f / (sqrtf(var) + 1e-8f);
    }
    __syncthreads();
    float mean = stats[0], rstd = stats[1];
    for (int i = tid; i < DD / 4; i += 256) {
        float4 v = *reinterpret_cast<const float4*>(rowbuf + i * 4);
        float o0 = (v.x - mean) * rstd * g[i * 4 + 0] + b[i * 4 + 0];
        float o1 = (v.y - mean) * rstd * g[i * 4 + 1] + b[i * 4 + 1];
        float o2 = (v.z - mean) * rstd * g[i * 4 + 2] + b[i * 4 + 2];
        float o3 = (v.w - mean) * rstd * g[i * 4 + 3] + b[i * 4 + 3];
        __half2* dst = reinterpret_cast<__half2*>(h2 + (size_t)row * DD + i * 4);
        dst[0] = __floats2half2_rn(o0, o1);
        dst[1] = __floats2half2_rn(o2, o3);
    }
}

// ---------------- split-K reduce (final, fp32 out) ----------------
__global__ void reduce2_kernel(const float* __restrict__ part, const float* __restrict__ bias,
                               const float* __restrict__ resid, float* __restrict__ out) {
    int i = blockIdx.x * 256 + threadIdx.x;
    const float4* p0 = reinterpret_cast<const float4*>(part);
    const float4* p1 = p0 + (TT * DD / 4);
    float4 a = p0[i], b = p1[i];
    int col = (i * 4) & (DD - 1);
    float4 bv = *reinterpret_cast<const float4*>(bias + col);
    float4 rv = reinterpret_cast<const float4*>(resid)[i];
    float4 o;
    o.x = a.x + b.x + bv.x + rv.x;
    o.y = a.y + b.y + bv.y + rv.y;
    o.z = a.z + b.z + bv.z + rv.z;
    o.w = a.w + b.w + bv.w + rv.w;
    reinterpret_cast<float4*>(out)[i] = o;
}

// ---------------- fp16 mma.sync GEMM (cp.async, BK=64, 2-stage, ldmatrix frags) ----------------
#define BM 128
#define BN 128
#define BK 64
#define LDS_ 72
#define GEMM_SMEM ((2 * BM * LDS_ + 2 * BN * LDS_) * 2)

template<bool GELU_, bool SPLIT, bool OUTH, bool QSC>
__global__ void __launch_bounds__(256, 2) mma_gemm(
    const __half* __restrict__ A, const __half* __restrict__ B0,
    const float* __restrict__ bias, const float* __restrict__ resid,
    void* Cv, int K, int lda, int ldb, int ldc)
{
    extern __shared__ __half hsm[];
    __half* Asm = hsm;
    __half* Bsm = hsm + 2 * BM * LDS_;

    if (SPLIT) {
        int z = blockIdx.z;
        A  += (size_t)z * K;
        B0 += (size_t)z * K;
        Cv = (void*)((float*)Cv + (size_t)z * TT * ldc);
    }

    int tid  = threadIdx.x;
    int warp = tid >> 5, lane = tid & 31;
    int wm = warp >> 2, wn = warp & 3;
    int g  = lane >> 2, tig = lane & 3;
    int lrow = lane & 15, lsel = lane >> 4;
    int rowBase = blockIdx.y * BM;
    int colBase = blockIdx.x * BN;
    int NC = K / BK;

    uint32_t abase = smem_u32(Asm);
    uint32_t bbase = smem_u32(Bsm);

    float acc[4][4][4];
    #pragma unroll
    for (int m = 0; m < 4; m++)
        #pragma unroll
        for (int n = 0; n < 4; n++)
            #pragma unroll
            for (int i = 0; i < 4; i++) acc[m][n][i] = 0.f;

    auto load_stage = [&](int c, int buf) {
        int k0 = c * BK;
        #pragma unroll
        for (int j = 0; j < 4; j++) {
            int f4 = j * 256 + tid;
            int r = f4 >> 3, cc = (f4 & 7) * 8;
            cp_async16(abase + (uint32_t)(buf * BM * LDS_ + r * LDS_ + cc) * 2,
                       A + (size_t)(rowBase + r) * lda + k0 + cc);
        }
        #pragma unroll
        for (int j = 0; j < 4; j++) {
            int f4 = j * 256 + tid;
            int r = f4 >> 3, cc = (f4 & 7) * 8;
            cp_async16(bbase + (uint32_t)(buf * BN * LDS_ + r * LDS_ + cc) * 2,
                       B0 + (size_t)(colBase + r) * ldb + k0 + cc);
        }
        CP_COMMIT();
    };

    auto compute = [&](int buf) {
        uint32_t As2 = abase + (uint32_t)(buf * BM * LDS_) * 2;
        uint32_t Bs2 = bbase + (uint32_t)(buf * BN * LDS_) * 2;
        #pragma unroll
        for (int kk = 0; kk < BK; kk += 16) {
            uint32_t af[4][4], bf[4][2];
            #pragma unroll
            for (int m = 0; m < 4; m++) {
                uint32_t a = As2 + (uint32_t)((wm * 64 + m * 16 + lrow) * LDS_ + kk + lsel * 8) * 2;
                ldsm_x4(af[m][0], af[m][1], af[m][2], af[m][3], a);
            }
            #pragma unroll
            for (int p = 0; p < 2; p++) {
                uint32_t a = Bs2 + (uint32_t)((wn * 32 + p * 16 + lrow) * LDS_ + kk + lsel * 8) * 2;
                ldsm_x4(bf[2 * p][0], bf[2 * p + 1][0], bf[2 * p][1], bf[2 * p + 1][1], a);
            }
            #pragma unroll
            for (int m = 0; m < 4; m++)
                #pragma unroll
                for (int n = 0; n < 4; n++)
                    mma_f16(acc[m][n], af[m], bf[n]);
        }
    };

    load_stage(0, 0);
    load_stage(1, 1);
    for (int c = 0; c < NC; c++) {
        if (c < NC - 1) { CP_WAIT1(); } else { CP_WAIT0(); }
        __syncthreads();
        compute(c & 1);
        __syncthreads();
        if (c + 2 <= NC - 1) load_stage(c + 2, c & 1);
    }

    const float SC = 0.18033688011112042f;  // 0.125 * log2(e) — folded into Q columns
    #pragma unroll
    for (int m = 0; m < 4; m++) {
        int r0 = rowBase + wm * 64 + m * 16 + g;
        #pragma unroll
        for (int n = 0; n < 4; n++) {
            int c0 = colBase + wn * 32 + n * 8 + tig * 2;
            #pragma unroll
            for (int half_ = 0; half_ < 2; half_++) {
                int r = r0 + half_ * 8;
                float v0 = acc[m][n][half_ * 2 + 0];
                float v1 = acc[m][n][half_ * 2 + 1];
                if (bias) { v0 += __ldg(bias + c0); v1 += __ldg(bias + c0 + 1); }
                if (GELU_) { v0 = gelu_f(v0); v1 = gelu_f(v1); }
                if (resid) {
                    float2 rv = *reinterpret_cast<const float2*>(resid + (size_t)r * ldc + c0);
                    v0 += rv.x; v1 += rv.y;
                }
                if (OUTH) {
                    if (QSC && colBase < 1024) { v0 *= SC; v1 *= SC; }
                    __half* Ch = (__half*)Cv + (size_t)r * ldc + c0;
                    *reinterpret_cast<__half2*>(Ch) = __floats2half2_rn(v0, v1);
                } else {
                    *reinterpret_cast<float2*>((float*)Cv + (size_t)r * ldc + c0) = make_float2(v0, v1);
                }
            }
        }
    }
}

// ---------------- fp16 mma.sync causal flash attention (ldmatrix frags) ----------------
#define QLD 72
#define KLD 72
#define VLD 72
#define AOFF_K (128 * QLD)
#define AOFF_V (AOFF_K + 2 * 64 * KLD)
#define ATT_SMEM ((AOFF_V + 2 * 64 * VLD) * 2)

__global__ void __launch_bounds__(256, 2) attn_mma(const __half* __restrict__ QKVp,
                                                   __half* __restrict__ ctx) {
    extern __shared__ __half smh[];
    __half* Qs = smh;            // 128 x QLD, reused as Ps
    __half* Ps = Qs;

    int qt = gridDim.x - 1 - blockIdx.x;
    int head = blockIdx.y;
    int tid = threadIdx.x, warp = tid >> 5, lane = tid & 31;
    int g = lane >> 2, tig = lane & 3;
    int lrow = lane & 15, lsel = lane >> 4;
    int m0 = warp * 16;
    int base = qt * 128;

    const __half* Qg = QKVp + (size_t)base * NQKV + head * 64;
    const __half* Kg = QKVp + 1024 + head * 64;
    const __half* Vg = QKVp + 2048 + head * 64;

    uint32_t qaddr = smem_u32(smh);
    uint32_t kaddr = smem_u32(smh + AOFF_K);
    uint32_t vaddr = smem_u32(smh + AOFF_V);

    auto load_tile = [&](int kt, int b) {
        const __half* Ksrc = Kg + (size_t)(kt * 64) * NQKV;
        const __half* Vsrc = Vg + (size_t)(kt * 64) * NQKV;
        uint32_t kb = kaddr + (uint32_t)(b * 64 * KLD) * 2;
        uint32_t vb = vaddr + (uint32_t)(b * 64 * VLD) * 2;
        #pragma unroll
        for (int j = 0; j < 2; j++) {
            int c = j * 256 + tid;
            int r = c >> 3, o = (c & 7) * 8;
            cp_async16(kb + (uint32_t)(r * KLD + o) * 2, Ksrc + (size_t)r * NQKV + o);
            cp_async16(vb + (uint32_t)(r * VLD + o) * 2, Vsrc + (size_t)r * NQKV + o);
        }
        CP_COMMIT();
    };

    int ktmax = (base + 127) >> 6;

    #pragma unroll
    for (int j = 0; j < 4; j++) {
        int c = j * 256 + tid;
        int r = c >> 3, o = (c & 7) * 8;
        cp_async16(qaddr + (uint32_t)(r * QLD + o) * 2, Qg + (size_t)r * NQKV + o);
    }
    CP_COMMIT();
    load_tile(0, 0);
    load_tile(1, 1);

    CP_WAIT2();
    __syncthreads();

    uint32_t qf[4][4];
    #pragma unroll
    for (int kc = 0; kc < 4; kc++) {
        uint32_t a = qaddr + (uint32_t)((m0 + lrow) * QLD + kc * 16 + lsel * 8) * 2;
        ldsm_x4(qf[kc][0], qf[kc][1], qf[kc][2], qf[kc][3], a);
    }
    __syncthreads();     // qf extracted before Ps overwrites Qs

    float mrow0 = -INFINITY, mrow1 = -INFINITY, lrow0 = 0.f, lrow1 = 0.f;
    float o[8][4];
    #pragma unroll
    for (int n = 0; n < 8; n++)
        #pragma unroll
        for (int i = 0; i < 4; i++) o[n][i] = 0.f;

    int q0 = base + m0 + g, q1 = q0 + 8;
    int qwmin = base + m0;
    int qwmax = base + m0 + 15;
    uint32_t lm_off = ((uint32_t)((lane & 15) * VLD + ((lane >> 4) & 1) * 8)) * 2;

    for (int kt = 0; kt <= ktmax; kt++) {
        int cur = kt & 1;
        if (kt < ktmax) { CP_WAIT1(); } else { CP_WAIT0(); }
        __syncthreads();

        uint32_t ktile = kaddr + (uint32_t)(cur * 64 * KLD) * 2;
        uint32_t vtile = vaddr + (uint32_t)(cur * 64 * VLD) * 2;

        if (kt * 64 <= qwmax) {
            // S = Q @ K^T (log2 units; Q pre-scaled)
            float s[8][4];
            #pragma unroll
            for (int n = 0; n < 8; n++)
                #pragma unroll
                for (int i = 0; i < 4; i++) s[n][i] = 0.f;
            #pragma unroll
            for (int kc = 0; kc < 4; kc++) {
                uint32_t bf[8][2];
                #pragma unroll
                for (int p = 0; p < 4; p++) {
                    uint32_t a = ktile + (uint32_t)((p * 16 + lrow) * KLD + kc * 16 + lsel * 8) * 2;
                    ldsm_x4(bf[2 * p][0], bf[2 * p + 1][0], bf[2 * p][1], bf[2 * p + 1][1], a);
                }
                #pragma unroll
                for (int n = 0; n < 8; n++)
                    mma_f16(s[n], qf[kc], bf[n]);
            }

            if (kt * 64 + 63 > qwmin) {
                #pragma unroll
                for (int n = 0; n < 8; n++) {
                    int k0 = kt * 64 + n * 8 + tig * 2;
                    if (k0     > q0) s[n][0] = -INFINITY;
                    if (k0 + 1 > q0) s[n][1] = -INFINITY;
                    if (k0     > q1) s[n][2] = -INFINITY;
                    if (k0 + 1 > q1) s[n][3] = -INFINITY;
                }
            }

            float mx0 = -INFINITY, mx1 = -INFINITY;
            #pragma unroll
            for (int n = 0; n < 8; n++) {
                mx0 = fmaxf(mx0, fmaxf(s[n][0], s[n][1]));
                mx1 = fmaxf(mx1, fmaxf(s[n][2], s[n][3]));
            }
            mx0 = fmaxf(mx0, __shfl_xor_sync(0xffffffffu, mx0, 1));
            mx0 = fmaxf(mx0, __shfl_xor_sync(0xffffffffu, mx0, 2));
            mx1 = fmaxf(mx1, __shfl_xor_sync(0xffffffffu, mx1, 1));
            mx1 = fmaxf(mx1, __shfl_xor_sync(0xffffffffu, mx1, 2));
            float mn0 = fmaxf(mrow0, mx0), mn1 = fmaxf(mrow1, mx1);
            float sc0 = ex2_fast(mrow0 - mn0), sc1 = ex2_fast(mrow1 - mn1);
            mrow0 = mn0; mrow1 = mn1;

            float ps0 = 0.f, ps1 = 0.f;
            #pragma unroll
            for (int n = 0; n < 8; n++) {
                float p0 = ex2_fast(s[n][0] - mn0);
                float p1 = ex2_fast(s[n][1] - mn0);
                float p2 = ex2_fast(s[n][2] - mn1);
                float p3 = ex2_fast(s[n][3] - mn1);
                ps0 += p0 + p1; ps1 += p2 + p3;
                *reinterpret_cast<__half2*>(&Ps[(m0 + g    ) * QLD + n * 8 + tig * 2]) =
                    __floats2half2_rn(p0, p1);
                *reinterpret_cast<__half2*>(&Ps[(m0 + g + 8) * QLD + n * 8 + tig * 2]) =
                    __floats2half2_rn(p2, p3);
            }
            ps0 += __shfl_xor_sync(0xffffffffu, ps0, 1);
            ps0 += __shfl_xor_sync(0xffffffffu, ps0, 2);
            ps1 += __shfl_xor_sync(0xffffffffu, ps1, 1);
            ps1 += __shfl_xor_sync(0xffffffffu, ps1, 2);
            lrow0 = lrow0 * sc0 + ps0;
            lrow1 = lrow1 * sc1 + ps1;

            #pragma unroll
            for (int n = 0; n < 8; n++) {
                o[n][0] *= sc0; o[n][1] *= sc0; o[n][2] *= sc1; o[n][3] *= sc1;
            }
            __syncwarp();

            // O += P @ V : P warp-private rows (ldmatrix); V via ldmatrix.trans
            #pragma unroll
            for (int kc = 0; kc < 4; kc++) {
                uint32_t pf[4];
                uint32_t pa = qaddr + (uint32_t)((m0 + lrow) * QLD + kc * 16 + lsel * 8) * 2;
                ldsm_x4(pf[0], pf[1], pf[2], pf[3], pa);
                #pragma unroll
                for (int nb = 0; nb < 4; nb++) {
                    uint32_t v0, v1, v2, v3;
                    uint32_t a = vtile + lm_off + (uint32_t)(kc * 16 * VLD + nb * 16) * 2;
                    asm volatile(
                        "ldmatrix.sync.aligned.m8n8.x4.trans.shared.b16 {%0,%1,%2,%3}, [%4];"
                        : "=r"(v0), "=r"(v1), "=r"(v2), "=r"(v3) : "r"(a));
                    uint32_t vfA[2] = {v0, v1};
                    uint32_t vfB[2] = {v2, v3};
                    mma_f16(o[nb * 2    ], pf, vfA);
                    mma_f16(o[nb * 2 + 1], pf, vfB);
                }
            }
        }
        __syncthreads();
        if (kt + 2 <= ktmax) load_tile(kt + 2, cur);
    }

    float rl0 = 1.f / lrow0, rl1 = 1.f / lrow1;
    __half* out0 = ctx + (size_t)q0 * DD + head * 64;
    __half* out1 = ctx + (size_t)q1 * DD + head * 64;
    #pragma unroll
    for (int n = 0; n < 8; n++) {
        int c = n * 8 + tig * 2;
        *reinterpret_cast<__half2*>(out0 + c) = __floats2half2_rn(o[n][0] * rl0, o[n][1] * rl0);
        *reinterpret_cast<__half2*>(out1 + c) = __floats2half2_rn(o[n][2] * rl1, o[n][3] * rl1);
    }
}

// ---------------- launch ----------------
extern "C" void kernel_launch(void* const* d_in, const int* in_sizes, int n_in,
                              void* d_out, int out_size) {
    const float* x     = (const float*)d_in[0];
    const float* wq    = (const float*)d_in[1];
    const float* wk    = (const float*)d_in[2];
    const float* wv    = (const float*)d_in[3];
    const float* wo    = (const float*)d_in[4];
    const float* bo    = (const float*)d_in[5];
    const float* ln1_g = (const float*)d_in[6];
    const float* ln1_b = (const float*)d_in[7];
    const float* ln2_g = (const float*)d_in[8];
    const float* ln2_b = (const float*)d_in[9];
    const float* w1    = (const float*)d_in[10];
    const float* b1    = (const float*)d_in[11];
    const float* w2    = (const float*)d_in[12];
    const float* b2    = (const float*)d_in[13];
    float* out = (float*)d_out;

    __half *h1, *qkv, *ctx, *h2, *ffn, *wt;
    float *x2, *part;
    cudaGetSymbolAddress((void**)&h1,   g_h1);
    cudaGetSymbolAddress((void**)&qkv,  g_qkv);
    cudaGetSymbolAddress((void**)&ctx,  g_ctx);
    cudaGetSymbolAddress((void**)&x2,   g_x2);
    cudaGetSymbolAddress((void**)&h2,   g_h2);
    cudaGetSymbolAddress((void**)&ffn,  g_ffn);
    cudaGetSymbolAddress((void**)&part, g_part);
    cudaGetSymbolAddress((void**)&wt,   g_wt);

    const int M1 = 1024 * 1024;
    const __half* wt_qkv = wt;
    const __half* wt_o   = wt + 3 * M1;
    const __half* wt_1   = wt + 4 * M1;
    const __half* wt_2   = wt + 8 * M1;

    cudaFuncSetAttribute(attn_mma, cudaFuncAttributeMaxDynamicSharedMemorySize, ATT_SMEM);
    cudaFuncSetAttribute(mma_gemm<false, false, true,  true >, cudaFuncAttributeMaxDynamicSharedMemorySize, GEMM_SMEM);
    cudaFuncSetAttribute(mma_gemm<false, true,  false, false>, cudaFuncAttributeMaxDynamicSharedMemorySize, GEMM_SMEM);
    cudaFuncSetAttribute(mma_gemm<true,  false, true,  false>, cudaFuncAttributeMaxDynamicSharedMemorySize, GEMM_SMEM);

    // wtrans (#1), LN1 (#2), QKV (#3) -> attention profiled in slot #4
    wtrans_kernel<<<12288, 256>>>(wq, wk, wv, wo, w1, w2, wt);
    ln_kernel<<<TT, 256>>>(x, ln1_g, ln1_b, h1);
    mma_gemm<false, false, true, true><<<dim3(NQKV / BN, TT / BM), 256, GEMM_SMEM>>>(
        h1, wt_qkv, nullptr, nullptr, qkv, DD, DD, DD, NQKV);
    attn_mma<<<dim3(TT / 128, HH), 256, ATT_SMEM>>>(qkv, ctx);
    mma_gemm<false, true, false, false><<<dim3(DD / BN, TT / BM, 2), 256, GEMM_SMEM>>>(
        ctx, wt_o, nullptr, nullptr, part, DD / 2, DD, DD, DD);
    reduce_ln<<<TT, 256>>>(part, bo, x, ln2_g, ln2_b, x2, h2);
    mma_gemm<true, false, true, false><<<dim3(DFF / BN, TT / BM), 256, GEMM_SMEM>>>(
        h2, wt_1, b1, nullptr, ffn, DD, DD, DD, DFF);
    mma_gemm<false, true, false, false><<<dim3(DD / BN, TT / BM, 2), 256, GEMM_SMEM>>>(
        ffn, wt_2, nullptr, nullptr, part, DFF / 2, DFF, DFF, DD);
    reduce2_kernel<<<TT * DD / 4 / 256, 256>>>(part, b2, x2, out);
}

// round 15
// speedup vs baseline: 1.0521x; 1.0521x over previous
#include <cuda_runtime.h>
#include <cuda_fp16.h>
#include <math.h>
#include <stdint.h>

#define TT   2048
#define DD   1024
#define HH   16
#define DH   64
#define DFF  4096
#define NQKV 3072

// ---------------- scratch ----------------
__device__ __half g_h1 [TT * DD];
__device__ __half g_qkv[TT * NQKV];
__device__ __half g_ctx[TT * DD];
__device__ float  g_x2 [TT * DD];
__device__ __half g_h2 [TT * DD];
__device__ __half g_ffn[TT * DFF];
__device__ float  g_part[2 * TT * DD];      // attention partials, then split-K GEMM partials
__device__ float  g_ml [2 * TT * HH * 2];   // attention (m, l) per split/row/head
__device__ __half g_wt [12 * 1024 * 1024];  // transposed fp16 weights

__device__ __forceinline__ float ex2_fast(float x) {
    float y;
    asm("ex2.approx.ftz.f32 %0, %1;" : "=f"(y) : "f"(x));
    return y;
}

__device__ __forceinline__ float gelu_f(float v) {
    return 0.5f * v * (1.0f + erff(v * 0.70710678118654752f));
}

__device__ __forceinline__ void mma_f16(float* c, const uint32_t* a, const uint32_t* b) {
    asm volatile(
        "mma.sync.aligned.m16n8k16.row.col.f32.f16.f16.f32 "
        "{%0,%1,%2,%3}, {%4,%5,%6,%7}, {%8,%9}, {%0,%1,%2,%3};"
        : "+f"(c[0]), "+f"(c[1]), "+f"(c[2]), "+f"(c[3])
        : "r"(a[0]), "r"(a[1]), "r"(a[2]), "r"(a[3]), "r"(b[0]), "r"(b[1]));
}

__device__ __forceinline__ void ldsm_x4(uint32_t& r0, uint32_t& r1, uint32_t& r2, uint32_t& r3,
                                        uint32_t addr) {
    asm volatile("ldmatrix.sync.aligned.m8n8.x4.shared.b16 {%0,%1,%2,%3}, [%4];"
                 : "=r"(r0), "=r"(r1), "=r"(r2), "=r"(r3) : "r"(addr));
}

__device__ __forceinline__ uint32_t smem_u32(const void* p) {
    uint32_t a;
    asm("{ .reg .u64 t; cvta.to.shared.u64 t, %1; cvt.u32.u64 %0, t; }" : "=r"(a) : "l"(p));
    return a;
}

__device__ __forceinline__ void cp_async16(uint32_t saddr, const void* gptr) {
    asm volatile("cp.async.cg.shared.global [%0], [%1], 16;" :: "r"(saddr), "l"(gptr) : "memory");
}
#define CP_COMMIT() asm volatile("cp.async.commit_group;" ::: "memory")
#define CP_WAIT0()  asm volatile("cp.async.wait_group 0;" ::: "memory")
#define CP_WAIT1()  asm volatile("cp.async.wait_group 1;" ::: "memory")
#define CP_WAIT2()  asm volatile("cp.async.wait_group 2;" ::: "memory")

// ---------------- weight transpose + RNE fp16 convert ----------------
__global__ void wtrans_kernel(const float* __restrict__ wq, const float* __restrict__ wk,
                              const float* __restrict__ wv, const float* __restrict__ wo,
                              const float* __restrict__ w1, const float* __restrict__ w2,
                              __half* __restrict__ dst) {
    __shared__ float tile[32][33];
    int t = blockIdx.x;
    const int T0 = 96 * 32, T1 = 32 * 32, T2 = 128 * 32;
    int nt, kt, Kd, Nfull, mode;
    const float* s1 = nullptr;
    __half* d;
    if (t < T0)                { mode = 0; nt = t / 32;  kt = t % 32;  d = dst;                 Kd = 1024; Nfull = 0; }
    else if (t < T0 + T1)      { t -= T0;       mode = 1; nt = t / 32;  kt = t % 32;  d = dst + 3 * 1024 * 1024; Kd = 1024; Nfull = 1024; s1 = wo; }
    else if (t < T0 + T1 + T2) { t -= T0 + T1;  mode = 2; nt = t / 32;  kt = t % 32;  d = dst + 4 * 1024 * 1024; Kd = 1024; Nfull = 4096; s1 = w1; }
    else                       { t -= T0 + T1 + T2; mode = 3; nt = t / 128; kt = t % 128; d = dst + 8 * 1024 * 1024; Kd = 4096; Nfull = 1024; s1 = w2; }

    int tx = threadIdx.x & 31, ty = threadIdx.x >> 5;
    #pragma unroll
    for (int i = 0; i < 4; i++) {
        int r = ty + i * 8;
        int k = kt * 32 + r;
        int n = nt * 32 + tx;
        float val;
        if (mode == 0) {
            int which = n >> 10, head = (n >> 6) & 15, e = n & 63;
            const float* w = (which == 0) ? wq : (which == 1) ? wk : wv;
            val = w[(size_t)head * (DD * DH) + (size_t)k * DH + e];
        } else {
            val = s1[(size_t)k * Nfull + n];
        }
        tile[r][tx] = val;
    }
    __syncthreads();
    #pragma unroll
    for (int i = 0; i < 4; i++) {
        int r = ty + i * 8;
        d[(size_t)(nt * 32 + r) * Kd + kt * 32 + tx] = __float2half_rn(tile[tx][r]);
    }
}

// ---------------- LayerNorm ----------------
__global__ void ln_kernel(const float* __restrict__ x, const float* __restrict__ g,
                          const float* __restrict__ b, __half* __restrict__ out) {
    int row = blockIdx.x;
    const float* xr = x + row * DD;
    float s = 0.f, s2 = 0.f;
    for (int i = threadIdx.x; i < DD; i += 256) { float v = xr[i]; s += v; s2 += v * v; }
    #pragma unroll
    for (int o = 16; o > 0; o >>= 1) {
        s  += __shfl_xor_sync(0xffffffffu, s,  o);
        s2 += __shfl_xor_sync(0xffffffffu, s2, o);
    }
    __shared__ float sm[8], sm2[8], stats[2];
    int w = threadIdx.x >> 5, lane = threadIdx.x & 31;
    if (lane == 0) { sm[w] = s; sm2[w] = s2; }
    __syncthreads();
    if (threadIdx.x == 0) {
        float ts = 0.f, ts2 = 0.f;
        #pragma unroll
        for (int i = 0; i < 8; i++) { ts += sm[i]; ts2 += sm2[i]; }
        float mean = ts / (float)DD;
        float var  = fmaxf((ts2 - (float)DD * mean * mean) / (float)(DD - 1), 0.f);
        stats[0] = mean; stats[1] = 1.f / (sqrtf(var) + 1e-8f);
    }
    __syncthreads();
    float mean = stats[0], rstd = stats[1];
    for (int i = threadIdx.x; i < DD / 2; i += 256) {
        float2 v = reinterpret_cast<const float2*>(xr)[i];
        float o0 = (v.x - mean) * rstd * g[i * 2] + b[i * 2];
        float o1 = (v.y - mean) * rstd * g[i * 2 + 1] + b[i * 2 + 1];
        reinterpret_cast<__half2*>(out + (size_t)row * DD)[i] = __floats2half2_rn(o0, o1);
    }
}

// ---------------- fused split-K reduce + LayerNorm ----------------
__global__ void reduce_ln(const float* __restrict__ part, const float* __restrict__ bias,
                          const float* __restrict__ resid, const float* __restrict__ g,
                          const float* __restrict__ b, float* __restrict__ x2,
                          __half* __restrict__ h2) {
    int row = blockIdx.x, tid = threadIdx.x;
    __shared__ float rowbuf[DD];
    __shared__ float sm1[8], sm2v[8], stats[2];
    const float4* p0 = reinterpret_cast<const float4*>(part) + (size_t)row * (DD / 4);
    const float4* p1 = reinterpret_cast<const float4*>(part) + (TT * DD / 4) + (size_t)row * (DD / 4);
    const float4* rv4 = reinterpret_cast<const float4*>(resid) + (size_t)row * (DD / 4);
    const float4* bv4 = reinterpret_cast<const float4*>(bias);
    float s = 0.f, s2 = 0.f;
    for (int i = tid; i < DD / 4; i += 256) {
        float4 a = p0[i], c = p1[i], bv = bv4[i], r = rv4[i];
        float4 v;
        v.x = a.x + c.x + bv.x + r.x; v.y = a.y + c.y + bv.y + r.y;
        v.z = a.z + c.z + bv.z + r.z; v.w = a.w + c.w + bv.w + r.w;
        reinterpret_cast<float4*>(x2 + (size_t)row * DD)[i] = v;
        *reinterpret_cast<float4*>(rowbuf + i * 4) = v;
        s += v.x + v.y + v.z + v.w;
        s2 += v.x * v.x + v.y * v.y + v.z * v.z + v.w * v.w;
    }
    #pragma unroll
    for (int o = 16; o > 0; o >>= 1) {
        s  += __shfl_xor_sync(0xffffffffu, s,  o);
        s2 += __shfl_xor_sync(0xffffffffu, s2, o);
    }
    int w = tid >> 5, lane = tid & 31;
    if (lane == 0) { sm1[w] = s; sm2v[w] = s2; }
    __syncthreads();
    if (tid == 0) {
        float ts = 0.f, ts2 = 0.f;
        #pragma unroll
        for (int i = 0; i < 8; i++) { ts += sm1[i]; ts2 += sm2v[i]; }
        float mean = ts / (float)DD;
        float var  = fmaxf((ts2 - (float)DD * mean * mean) / (float)(DD - 1), 0.f);
        stats[0] = mean; stats[1] = 1.f / (sqrtf(var) + 1e-8f);
    }
    __syncthreads();
    float mean = stats[0], rstd = stats[1];
    for (int i = tid; i < DD / 4; i += 256) {
        float4 v = *reinterpret_cast<const float4*>(rowbuf + i * 4);
        float o0 = (v.x - mean) * rstd * g[i * 4 + 0] + b[i * 4 + 0];
        float o1 = (v.y - mean) * rstd * g[i * 4 + 1] + b[i * 4 + 1];
        float o2 = (v.z - mean) * rstd * g[i * 4 + 2] + b[i * 4 + 2];
        float o3 = (v.w - mean) * rstd * g[i * 4 + 3] + b[i * 4 + 3];
        __half2* dst = reinterpret_cast<__half2*>(h2 + (size_t)row * DD + i * 4);
        dst[0] = __floats2half2_rn(o0, o1);
        dst[1] = __floats2half2_rn(o2, o3);
    }
}

// ---------------- split-K reduce (final, fp32 out) ----------------
__global__ void reduce2_kernel(const float* __restrict__ part, const float* __restrict__ bias,
                               const float* __restrict__ resid, float* __restrict__ out) {
    int i = blockIdx.x * 256 + threadIdx.x;
    const float4* p0 = reinterpret_cast<const float4*>(part);
    const float4* p1 = p0 + (TT * DD / 4);
    float4 a = p0[i], b = p1[i];
    int col = (i * 4) & (DD - 1);
    float4 bv = *reinterpret_cast<const float4*>(bias + col);
    float4 rv = reinterpret_cast<const float4*>(resid)[i];
    float4 o;
    o.x = a.x + b.x + bv.x + rv.x;
    o.y = a.y + b.y + bv.y + rv.y;
    o.z = a.z + b.z + bv.z + rv.z;
    o.w = a.w + b.w + bv.w + rv.w;
    reinterpret_cast<float4*>(out)[i] = o;
}

// ---------------- attention combine: merge 2 KV-splits ----------------
__global__ void attn_combine(const float* __restrict__ part, const float* __restrict__ ml,
                             __half* __restrict__ ctx) {
    int row = blockIdx.x, tid = threadIdx.x;
    int col = tid * 4;
    int head = col >> 6;
    const float* m0p = ml + ((size_t)row * HH + head) * 2;
    const float* m1p = ml + ((size_t)(TT + row) * HH + head) * 2;
    float m0 = m0p[0], l0 = m0p[1], m1 = m1p[0], l1 = m1p[1];
    float m = fmaxf(m0, m1);
    float a0 = ex2_fast(m0 - m), a1 = ex2_fast(m1 - m);
    float rl = 1.f / (l0 * a0 + l1 * a1);
    float4 p0 = *reinterpret_cast<const float4*>(part + (size_t)row * DD + col);
    float4 p1 = *reinterpret_cast<const float4*>(part + (size_t)TT * DD + (size_t)row * DD + col);
    float v0 = (p0.x * a0 + p1.x * a1) * rl;
    float v1 = (p0.y * a0 + p1.y * a1) * rl;
    float v2 = (p0.z * a0 + p1.z * a1) * rl;
    float v3 = (p0.w * a0 + p1.w * a1) * rl;
    __half2* dst = reinterpret_cast<__half2*>(ctx + (size_t)row * DD + col);
    dst[0] = __floats2half2_rn(v0, v1);
    dst[1] = __floats2half2_rn(v2, v3);
}

// ---------------- fp16 mma.sync GEMM (cp.async, BK=64, 2-stage, ldmatrix) ----------------
#define BM 128
#define BN 128
#define BK 64
#define LDS_ 72
#define GEMM_SMEM ((2 * BM * LDS_ + 2 * BN * LDS_) * 2)

template<bool GELU_, bool SPLIT, bool OUTH, bool QSC>
__global__ void __launch_bounds__(256, 2) mma_gemm(
    const __half* __restrict__ A, const __half* __restrict__ B0,
    const float* __restrict__ bias, const float* __restrict__ resid,
    void* Cv, int K, int lda, int ldb, int ldc)
{
    extern __shared__ __half hsm[];
    __half* Asm = hsm;
    __half* Bsm = hsm + 2 * BM * LDS_;

    if (SPLIT) {
        int z = blockIdx.z;
        A  += (size_t)z * K;
        B0 += (size_t)z * K;
        Cv = (void*)((float*)Cv + (size_t)z * TT * ldc);
    }

    int tid  = threadIdx.x;
    int warp = tid >> 5, lane = tid & 31;
    int wm = warp >> 2, wn = warp & 3;
    int g  = lane >> 2, tig = lane & 3;
    int lrow = lane & 15, lsel = lane >> 4;
    int rowBase = blockIdx.y * BM;
    int colBase = blockIdx.x * BN;
    int NC = K / BK;

    uint32_t abase = smem_u32(Asm);
    uint32_t bbase = smem_u32(Bsm);

    float acc[4][4][4];
    #pragma unroll
    for (int m = 0; m < 4; m++)
        #pragma unroll
        for (int n = 0; n < 4; n++)
            #pragma unroll
            for (int i = 0; i < 4; i++) acc[m][n][i] = 0.f;

    auto load_stage = [&](int c, int buf) {
        int k0 = c * BK;
        #pragma unroll
        for (int j = 0; j < 4; j++) {
            int f4 = j * 256 + tid;
            int r = f4 >> 3, cc = (f4 & 7) * 8;
            cp_async16(abase + (uint32_t)(buf * BM * LDS_ + r * LDS_ + cc) * 2,
                       A + (size_t)(rowBase + r) * lda + k0 + cc);
        }
        #pragma unroll
        for (int j = 0; j < 4; j++) {
            int f4 = j * 256 + tid;
            int r = f4 >> 3, cc = (f4 & 7) * 8;
            cp_async16(bbase + (uint32_t)(buf * BN * LDS_ + r * LDS_ + cc) * 2,
                       B0 + (size_t)(colBase + r) * ldb + k0 + cc);
        }
        CP_COMMIT();
    };

    auto compute = [&](int buf) {
        uint32_t As2 = abase + (uint32_t)(buf * BM * LDS_) * 2;
        uint32_t Bs2 = bbase + (uint32_t)(buf * BN * LDS_) * 2;
        #pragma unroll
        for (int kk = 0; kk < BK; kk += 16) {
            uint32_t af[4][4], bf[4][2];
            #pragma unroll
            for (int m = 0; m < 4; m++) {
                uint32_t a = As2 + (uint32_t)((wm * 64 + m * 16 + lrow) * LDS_ + kk + lsel * 8) * 2;
                ldsm_x4(af[m][0], af[m][1], af[m][2], af[m][3], a);
            }
            #pragma unroll
            for (int p = 0; p < 2; p++) {
                uint32_t a = Bs2 + (uint32_t)((wn * 32 + p * 16 + lrow) * LDS_ + kk + lsel * 8) * 2;
                ldsm_x4(bf[2 * p][0], bf[2 * p + 1][0], bf[2 * p][1], bf[2 * p + 1][1], a);
            }
            #pragma unroll
            for (int m = 0; m < 4; m++)
                #pragma unroll
                for (int n = 0; n < 4; n++)
                    mma_f16(acc[m][n], af[m], bf[n]);
        }
    };

    load_stage(0, 0);
    load_stage(1, 1);
    for (int c = 0; c < NC; c++) {
        if (c < NC - 1) { CP_WAIT1(); } else { CP_WAIT0(); }
        __syncthreads();
        compute(c & 1);
        __syncthreads();
        if (c + 2 <= NC - 1) load_stage(c + 2, c & 1);
    }

    const float SC = 0.18033688011112042f;  // 0.125 * log2(e)
    #pragma unroll
    for (int m = 0; m < 4; m++) {
        int r0 = rowBase + wm * 64 + m * 16 + g;
        #pragma unroll
        for (int n = 0; n < 4; n++) {
            int c0 = colBase + wn * 32 + n * 8 + tig * 2;
            #pragma unroll
            for (int half_ = 0; half_ < 2; half_++) {
                int r = r0 + half_ * 8;
                float v0 = acc[m][n][half_ * 2 + 0];
                float v1 = acc[m][n][half_ * 2 + 1];
                if (bias) { v0 += __ldg(bias + c0); v1 += __ldg(bias + c0 + 1); }
                if (GELU_) { v0 = gelu_f(v0); v1 = gelu_f(v1); }
                if (resid) {
                    float2 rv = *reinterpret_cast<const float2*>(resid + (size_t)r * ldc + c0);
                    v0 += rv.x; v1 += rv.y;
                }
                if (OUTH) {
                    if (QSC && colBase < 1024) { v0 *= SC; v1 *= SC; }
                    __half* Ch = (__half*)Cv + (size_t)r * ldc + c0;
                    *reinterpret_cast<__half2*>(Ch) = __floats2half2_rn(v0, v1);
                } else {
                    *reinterpret_cast<float2*>((float*)Cv + (size_t)r * ldc + c0) = make_float2(v0, v1);
                }
            }
        }
    }
}

// ---------------- fp16 causal flash attention, KV-split=2, partial outputs ----------------
#define QLD 72
#define KLD 72
#define VLD 72
#define AOFF_K (128 * QLD)
#define AOFF_V (AOFF_K + 2 * 64 * KLD)
#define ATT_SMEM ((AOFF_V + 2 * 64 * VLD) * 2)

__global__ void __launch_bounds__(256, 2) attn_mma(const __half* __restrict__ QKVp,
                                                   float* __restrict__ part,
                                                   float* __restrict__ ml) {
    extern __shared__ __half smh[];
    __half* Qs = smh;            // 128 x QLD, reused as Ps
    __half* Ps = Qs;

    int qt = gridDim.x - 1 - blockIdx.x;
    int head = blockIdx.y;
    int z = blockIdx.z;
    int tid = threadIdx.x, warp = tid >> 5, lane = tid & 31;
    int g = lane >> 2, tig = lane & 3;
    int lrow = lane & 15, lsel = lane >> 4;
    int m0 = warp * 16;
    int base = qt * 128;

    int ntiles = ((base + 127) >> 6) + 1;
    int halfN = (ntiles + 1) >> 1;
    int t0 = z ? halfN : 0;
    int t1 = z ? ntiles : halfN;

    const __half* Qg = QKVp + (size_t)base * NQKV + head * 64;
    const __half* Kg = QKVp + 1024 + head * 64;
    const __half* Vg = QKVp + 2048 + head * 64;

    uint32_t qaddr = smem_u32(smh);
    uint32_t kaddr = smem_u32(smh + AOFF_K);
    uint32_t vaddr = smem_u32(smh + AOFF_V);

    auto load_tile = [&](int kt, int b) {
        const __half* Ksrc = Kg + (size_t)(kt * 64) * NQKV;
        const __half* Vsrc = Vg + (size_t)(kt * 64) * NQKV;
        uint32_t kb = kaddr + (uint32_t)(b * 64 * KLD) * 2;
        uint32_t vb = vaddr + (uint32_t)(b * 64 * VLD) * 2;
        #pragma unroll
        for (int j = 0; j < 2; j++) {
            int c = j * 256 + tid;
            int r = c >> 3, o = (c & 7) * 8;
            cp_async16(kb + (uint32_t)(r * KLD + o) * 2, Ksrc + (size_t)r * NQKV + o);
            cp_async16(vb + (uint32_t)(r * VLD + o) * 2, Vsrc + (size_t)r * NQKV + o);
        }
        CP_COMMIT();
    };

    #pragma unroll
    for (int j = 0; j < 4; j++) {
        int c = j * 256 + tid;
        int r = c >> 3, o = (c & 7) * 8;
        cp_async16(qaddr + (uint32_t)(r * QLD + o) * 2, Qg + (size_t)r * NQKV + o);
    }
    CP_COMMIT();
    load_tile(t0, 0);
    if (t0 + 1 < t1) load_tile(t0 + 1, 1);

    if (t0 + 1 < t1) { CP_WAIT2(); } else { CP_WAIT1(); }
    __syncthreads();

    uint32_t qf[4][4];
    #pragma unroll
    for (int kc = 0; kc < 4; kc++) {
        uint32_t a = qaddr + (uint32_t)((m0 + lrow) * QLD + kc * 16 + lsel * 8) * 2;
        ldsm_x4(qf[kc][0], qf[kc][1], qf[kc][2], qf[kc][3], a);
    }
    __syncthreads();     // qf extracted before Ps overwrites Qs

    float mrow0 = -INFINITY, mrow1 = -INFINITY, lrow0v = 0.f, lrow1v = 0.f;
    float o[8][4];
    #pragma unroll
    for (int n = 0; n < 8; n++)
        #pragma unroll
        for (int i = 0; i < 4; i++) o[n][i] = 0.f;

    int q0 = base + m0 + g, q1 = q0 + 8;
    int qwmin = base + m0;
    int qwmax = base + m0 + 15;
    uint32_t lm_off = ((uint32_t)((lane & 15) * VLD + ((lane >> 4) & 1) * 8)) * 2;

    for (int kt = t0; kt < t1; kt++) {
        int cur = (kt - t0) & 1;
        if (kt < t1 - 1) { CP_WAIT1(); } else { CP_WAIT0(); }
        __syncthreads();

        uint32_t ktile = kaddr + (uint32_t)(cur * 64 * KLD) * 2;
        uint32_t vtile = vaddr + (uint32_t)(cur * 64 * VLD) * 2;

        if (kt * 64 <= qwmax) {
            float s[8][4];
            #pragma unroll
            for (int n = 0; n < 8; n++)
                #pragma unroll
                for (int i = 0; i < 4; i++) s[n][i] = 0.f;
            #pragma unroll
            for (int kc = 0; kc < 4; kc++) {
                uint32_t bf[8][2];
                #pragma unroll
                for (int p = 0; p < 4; p++) {
                    uint32_t a = ktile + (uint32_t)((p * 16 + lrow) * KLD + kc * 16 + lsel * 8) * 2;
                    ldsm_x4(bf[2 * p][0], bf[2 * p + 1][0], bf[2 * p][1], bf[2 * p + 1][1], a);
                }
                #pragma unroll
                for (int n = 0; n < 8; n++)
                    mma_f16(s[n], qf[kc], bf[n]);
            }

            if (kt * 64 + 63 > qwmin) {
                #pragma unroll
                for (int n = 0; n < 8; n++) {
                    int k0 = kt * 64 + n * 8 + tig * 2;
                    if (k0     > q0) s[n][0] = -INFINITY;
                    if (k0 + 1 > q0) s[n][1] = -INFINITY;
                    if (k0     > q1) s[n][2] = -INFINITY;
                    if (k0 + 1 > q1) s[n][3] = -INFINITY;
                }
            }

            float mx0 = -INFINITY, mx1 = -INFINITY;
            #pragma unroll
            for (int n = 0; n < 8; n++) {
                mx0 = fmaxf(mx0, fmaxf(s[n][0], s[n][1]));
                mx1 = fmaxf(mx1, fmaxf(s[n][2], s[n][3]));
            }
            mx0 = fmaxf(mx0, __shfl_xor_sync(0xffffffffu, mx0, 1));
            mx0 = fmaxf(mx0, __shfl_xor_sync(0xffffffffu, mx0, 2));
            mx1 = fmaxf(mx1, __shfl_xor_sync(0xffffffffu, mx1, 1));
            mx1 = fmaxf(mx1, __shfl_xor_sync(0xffffffffu, mx1, 2));
            float mn0 = fmaxf(mrow0, mx0), mn1 = fmaxf(mrow1, mx1);
            float sc0 = ex2_fast(mrow0 - mn0), sc1 = ex2_fast(mrow1 - mn1);
            mrow0 = mn0; mrow1 = mn1;

            float ps0 = 0.f, ps1 = 0.f;
            #pragma unroll
            for (int n = 0; n < 8; n++) {
                float p0 = ex2_fast(s[n][0] - mn0);
                float p1 = ex2_fast(s[n][1] - mn0);
                float p2 = ex2_fast(s[n][2] - mn1);
                float p3 = ex2_fast(s[n][3] - mn1);
                ps0 += p0 + p1; ps1 += p2 + p3;
                *reinterpret_cast<__half2*>(&Ps[(m0 + g    ) * QLD + n * 8 + tig * 2]) =
                    __floats2half2_rn(p0, p1);
                *reinterpret_cast<__half2*>(&Ps[(m0 + g + 8) * QLD + n * 8 + tig * 2]) =
                    __floats2half2_rn(p2, p3);
            }
            ps0 += __shfl_xor_sync(0xffffffffu, ps0, 1);
            ps0 += __shfl_xor_sync(0xffffffffu, ps0, 2);
            ps1 += __shfl_xor_sync(0xffffffffu, ps1, 1);
            ps1 += __shfl_xor_sync(0xffffffffu, ps1, 2);
            lrow0v = lrow0v * sc0 + ps0;
            lrow1v = lrow1v * sc1 + ps1;

            #pragma unroll
            for (int n = 0; n < 8; n++) {
                o[n][0] *= sc0; o[n][1] *= sc0; o[n][2] *= sc1; o[n][3] *= sc1;
            }
            __syncwarp();

            #pragma unroll
            for (int kc = 0; kc < 4; kc++) {
                uint32_t pf[4];
                uint32_t pa = qaddr + (uint32_t)((m0 + lrow) * QLD + kc * 16 + lsel * 8) * 2;
                ldsm_x4(pf[0], pf[1], pf[2], pf[3], pa);
                #pragma unroll
                for (int nb = 0; nb < 4; nb++) {
                    uint32_t v0, v1, v2, v3;
                    uint32_t a = vtile + lm_off + (uint32_t)(kc * 16 * VLD + nb * 16) * 2;
                    asm volatile(
                        "ldmatrix.sync.aligned.m8n8.x4.trans.shared.b16 {%0,%1,%2,%3}, [%4];"
                        : "=r"(v0), "=r"(v1), "=r"(v2), "=r"(v3) : "r"(a));
                    uint32_t vfA[2] = {v0, v1};
                    uint32_t vfB[2] = {v2, v3};
                    mma_f16(o[nb * 2    ], pf, vfA);
                    mma_f16(o[nb * 2 + 1], pf, vfB);
                }
            }
        }
        __syncthreads();
        if (kt + 2 < t1) load_tile(kt + 2, cur);
    }

    // write unnormalized partials + (m, l)
    float* po = part + (size_t)z * TT * DD;
    if (tig == 0) {
        float* mp0 = ml + ((size_t)(z * TT + q0) * HH + head) * 2;
        float* mp1 = ml + ((size_t)(z * TT + q1) * HH + head) * 2;
        mp0[0] = mrow0; mp0[1] = lrow0v;
        mp1[0] = mrow1; mp1[1] = lrow1v;
    }
    float* out0 = po + (size_t)q0 * DD + head * 64;
    float* out1 = po + (size_t)q1 * DD + head * 64;
    #pragma unroll
    for (int n = 0; n < 8; n++) {
        int c = n * 8 + tig * 2;
        *reinterpret_cast<float2*>(out0 + c) = make_float2(o[n][0], o[n][1]);
        *reinterpret_cast<float2*>(out1 + c) = make_float2(o[n][2], o[n][3]);
    }
}

// ---------------- launch ----------------
extern "C" void kernel_launch(void* const* d_in, const int* in_sizes, int n_in,
                              void* d_out, int out_size) {
    const float* x     = (const float*)d_in[0];
    const float* wq    = (const float*)d_in[1];
    const float* wk    = (const float*)d_in[2];
    const float* wv    = (const float*)d_in[3];
    const float* wo    = (const float*)d_in[4];
    const float* bo    = (const float*)d_in[5];
    const float* ln1_g = (const float*)d_in[6];
    const float* ln1_b = (const float*)d_in[7];
    const float* ln2_g = (const float*)d_in[8];
    const float* ln2_b = (const float*)d_in[9];
    const float* w1    = (const float*)d_in[10];
    const float* b1    = (const float*)d_in[11];
    const float* w2    = (const float*)d_in[12];
    const float* b2    = (const float*)d_in[13];
    float* out = (float*)d_out;

    __half *h1, *qkv, *ctx, *h2, *ffn, *wt;
    float *x2, *part, *ml;
    cudaGetSymbolAddress((void**)&h1,   g_h1);
    cudaGetSymbolAddress((void**)&qkv,  g_qkv);
    cudaGetSymbolAddress((void**)&ctx,  g_ctx);
    cudaGetSymbolAddress((void**)&x2,   g_x2);
    cudaGetSymbolAddress((void**)&h2,   g_h2);
    cudaGetSymbolAddress((void**)&ffn,  g_ffn);
    cudaGetSymbolAddress((void**)&part, g_part);
    cudaGetSymbolAddress((void**)&ml,   g_ml);
    cudaGetSymbolAddress((void**)&wt,   g_wt);

    const int M1 = 1024 * 1024;
    const __half* wt_qkv = wt;
    const __half* wt_o   = wt + 3 * M1;
    const __half* wt_1   = wt + 4 * M1;
    const __half* wt_2   = wt + 8 * M1;

    cudaFuncSetAttribute(attn_mma, cudaFuncAttributeMaxDynamicSharedMemorySize, ATT_SMEM);
    cudaFuncSetAttribute(mma_gemm<false, false, true,  true >, cudaFuncAttributeMaxDynamicSharedMemorySize, GEMM_SMEM);
    cudaFuncSetAttribute(mma_gemm<false, true,  false, false>, cudaFuncAttributeMaxDynamicSharedMemorySize, GEMM_SMEM);
    cudaFuncSetAttribute(mma_gemm<true,  false, true,  false>, cudaFuncAttributeMaxDynamicSharedMemorySize, GEMM_SMEM);

    // wtrans (#1), LN1 (#2), QKV (#3), attention (#4 — profiled)
    wtrans_kernel<<<12288, 256>>>(wq, wk, wv, wo, w1, w2, wt);
    ln_kernel<<<TT, 256>>>(x, ln1_g, ln1_b, h1);
    mma_gemm<false, false, true, true><<<dim3(NQKV / BN, TT / BM), 256, GEMM_SMEM>>>(
        h1, wt_qkv, nullptr, nullptr, qkv, DD, DD, DD, NQKV);
    attn_mma<<<dim3(TT / 128, HH, 2), 256, ATT_SMEM>>>(qkv, part, ml);
    attn_combine<<<TT, 256>>>(part, ml, ctx);
    mma_gemm<false, true, false, false><<<dim3(DD / BN, TT / BM, 2), 256, GEMM_SMEM>>>(
        ctx, wt_o, nullptr, nullptr, part, DD / 2, DD, DD, DD);
    reduce_ln<<<TT, 256>>>(part, bo, x, ln2_g, ln2_b, x2, h2);
    mma_gemm<true, false, true, false><<<dim3(DFF / BN, TT / BM), 256, GEMM_SMEM>>>(
        h2, wt_1, b1, nullptr, ffn, DD, DD, DD, DFF);
    mma_gemm<false, true, false, false><<<dim3(DD / BN, TT / BM, 2), 256, GEMM_SMEM>>>(
        ffn, wt_2, nullptr, nullptr, part, DFF / 2, DFF, DFF, DD);
    reduce2_kernel<<<TT * DD / 4 / 256, 256>>>(part, b2, x2, out);
}

// round 16
// speedup vs baseline: 1.0674x; 1.0146x over previous
#include <cuda_runtime.h>
#include <cuda_fp16.h>
#include <math.h>
#include <stdint.h>

#define TT   2048
#define DD   1024
#define HH   16
#define DH   64
#define DFF  4096
#define NQKV 3072
#define NSPL 4

// ---------------- scratch ----------------
__device__ __half g_h1 [TT * DD];
__device__ __half g_qkv[TT * NQKV];
__device__ __half g_ctx[TT * DD];
__device__ float  g_x2 [TT * DD];
__device__ __half g_h2 [TT * DD];
__device__ __half g_ffn[TT * DFF];
__device__ float  g_part[NSPL * TT * DD];      // attention partials / split-K GEMM partials
__device__ float  g_ml [NSPL * TT * HH * 2];   // attention (m, l)
__device__ __half g_wt [12 * 1024 * 1024];     // transposed fp16 weights

__device__ __forceinline__ float ex2_fast(float x) {
    float y;
    asm("ex2.approx.ftz.f32 %0, %1;" : "=f"(y) : "f"(x));
    return y;
}

__device__ __forceinline__ float gelu_f(float v) {
    return 0.5f * v * (1.0f + erff(v * 0.70710678118654752f));
}

__device__ __forceinline__ void mma_f16(float* c, const uint32_t* a, const uint32_t* b) {
    asm volatile(
        "mma.sync.aligned.m16n8k16.row.col.f32.f16.f16.f32 "
        "{%0,%1,%2,%3}, {%4,%5,%6,%7}, {%8,%9}, {%0,%1,%2,%3};"
        : "+f"(c[0]), "+f"(c[1]), "+f"(c[2]), "+f"(c[3])
        : "r"(a[0]), "r"(a[1]), "r"(a[2]), "r"(a[3]), "r"(b[0]), "r"(b[1]));
}

__device__ __forceinline__ void ldsm_x4(uint32_t& r0, uint32_t& r1, uint32_t& r2, uint32_t& r3,
                                        uint32_t addr) {
    asm volatile("ldmatrix.sync.aligned.m8n8.x4.shared.b16 {%0,%1,%2,%3}, [%4];"
                 : "=r"(r0), "=r"(r1), "=r"(r2), "=r"(r3) : "r"(addr));
}

__device__ __forceinline__ uint32_t smem_u32(const void* p) {
    uint32_t a;
    asm("{ .reg .u64 t; cvta.to.shared.u64 t, %1; cvt.u32.u64 %0, t; }" : "=r"(a) : "l"(p));
    return a;
}

__device__ __forceinline__ void cp_async16(uint32_t saddr, const void* gptr) {
    asm volatile("cp.async.cg.shared.global [%0], [%1], 16;" :: "r"(saddr), "l"(gptr) : "memory");
}
#define CP_COMMIT() asm volatile("cp.async.commit_group;" ::: "memory")
#define CP_WAIT0()  asm volatile("cp.async.wait_group 0;" ::: "memory")
#define CP_WAIT1()  asm volatile("cp.async.wait_group 1;" ::: "memory")
#define CP_WAIT2()  asm volatile("cp.async.wait_group 2;" ::: "memory")

// ---------------- weight transpose + RNE fp16 convert ----------------
__global__ void wtrans_kernel(const float* __restrict__ wq, const float* __restrict__ wk,
                              const float* __restrict__ wv, const float* __restrict__ wo,
                              const float* __restrict__ w1, const float* __restrict__ w2,
                              __half* __restrict__ dst) {
    __shared__ float tile[32][33];
    int t = blockIdx.x;
    const int T0 = 96 * 32, T1 = 32 * 32, T2 = 128 * 32;
    int nt, kt, Kd, Nfull, mode;
    const float* s1 = nullptr;
    __half* d;
    if (t < T0)                { mode = 0; nt = t / 32;  kt = t % 32;  d = dst;                 Kd = 1024; Nfull = 0; }
    else if (t < T0 + T1)      { t -= T0;       mode = 1; nt = t / 32;  kt = t % 32;  d = dst + 3 * 1024 * 1024; Kd = 1024; Nfull = 1024; s1 = wo; }
    else if (t < T0 + T1 + T2) { t -= T0 + T1;  mode = 2; nt = t / 32;  kt = t % 32;  d = dst + 4 * 1024 * 1024; Kd = 1024; Nfull = 4096; s1 = w1; }
    else                       { t -= T0 + T1 + T2; mode = 3; nt = t / 128; kt = t % 128; d = dst + 8 * 1024 * 1024; Kd = 4096; Nfull = 1024; s1 = w2; }

    int tx = threadIdx.x & 31, ty = threadIdx.x >> 5;
    #pragma unroll
    for (int i = 0; i < 4; i++) {
        int r = ty + i * 8;
        int k = kt * 32 + r;
        int n = nt * 32 + tx;
        float val;
        if (mode == 0) {
            int which = n >> 10, head = (n >> 6) & 15, e = n & 63;
            const float* w = (which == 0) ? wq : (which == 1) ? wk : wv;
            val = w[(size_t)head * (DD * DH) + (size_t)k * DH + e];
        } else {
            val = s1[(size_t)k * Nfull + n];
        }
        tile[r][tx] = val;
    }
    __syncthreads();
    #pragma unroll
    for (int i = 0; i < 4; i++) {
        int r = ty + i * 8;
        d[(size_t)(nt * 32 + r) * Kd + kt * 32 + tx] = __float2half_rn(tile[tx][r]);
    }
}

// ---------------- LayerNorm ----------------
__global__ void ln_kernel(const float* __restrict__ x, const float* __restrict__ g,
                          const float* __restrict__ b, __half* __restrict__ out) {
    int row = blockIdx.x;
    const float* xr = x + row * DD;
    float s = 0.f, s2 = 0.f;
    for (int i = threadIdx.x; i < DD; i += 256) { float v = xr[i]; s += v; s2 += v * v; }
    #pragma unroll
    for (int o = 16; o > 0; o >>= 1) {
        s  += __shfl_xor_sync(0xffffffffu, s,  o);
        s2 += __shfl_xor_sync(0xffffffffu, s2, o);
    }
    __shared__ float sm[8], sm2[8], stats[2];
    int w = threadIdx.x >> 5, lane = threadIdx.x & 31;
    if (lane == 0) { sm[w] = s; sm2[w] = s2; }
    __syncthreads();
    if (threadIdx.x == 0) {
        float ts = 0.f, ts2 = 0.f;
        #pragma unroll
        for (int i = 0; i < 8; i++) { ts += sm[i]; ts2 += sm2[i]; }
        float mean = ts / (float)DD;
        float var  = fmaxf((ts2 - (float)DD * mean * mean) / (float)(DD - 1), 0.f);
        stats[0] = mean; stats[1] = 1.f / (sqrtf(var) + 1e-8f);
    }
    __syncthreads();
    float mean = stats[0], rstd = stats[1];
    for (int i = threadIdx.x; i < DD / 2; i += 256) {
        float2 v = reinterpret_cast<const float2*>(xr)[i];
        float o0 = (v.x - mean) * rstd * g[i * 2] + b[i * 2];
        float o1 = (v.y - mean) * rstd * g[i * 2 + 1] + b[i * 2 + 1];
        reinterpret_cast<__half2*>(out + (size_t)row * DD)[i] = __floats2half2_rn(o0, o1);
    }
}

// ---------------- fused split-K reduce + LayerNorm ----------------
__global__ void reduce_ln(const float* __restrict__ part, const float* __restrict__ bias,
                          const float* __restrict__ resid, const float* __restrict__ g,
                          const float* __restrict__ b, float* __restrict__ x2,
                          __half* __restrict__ h2) {
    int row = blockIdx.x, tid = threadIdx.x;
    __shared__ float rowbuf[DD];
    __shared__ float sm1[8], sm2v[8], stats[2];
    const float4* p0 = reinterpret_cast<const float4*>(part) + (size_t)row * (DD / 4);
    const float4* p1 = reinterpret_cast<const float4*>(part) + (TT * DD / 4) + (size_t)row * (DD / 4);
    const float4* rv4 = reinterpret_cast<const float4*>(resid) + (size_t)row * (DD / 4);
    const float4* bv4 = reinterpret_cast<const float4*>(bias);
    float s = 0.f, s2 = 0.f;
    for (int i = tid; i < DD / 4; i += 256) {
        float4 a = p0[i], c = p1[i], bv = bv4[i], r = rv4[i];
        float4 v;
        v.x = a.x + c.x + bv.x + r.x; v.y = a.y + c.y + bv.y + r.y;
        v.z = a.z + c.z + bv.z + r.z; v.w = a.w + c.w + bv.w + r.w;
        reinterpret_cast<float4*>(x2 + (size_t)row * DD)[i] = v;
        *reinterpret_cast<float4*>(rowbuf + i * 4) = v;
        s += v.x + v.y + v.z + v.w;
        s2 += v.x * v.x + v.y * v.y + v.z * v.z + v.w * v.w;
    }
    #pragma unroll
    for (int o = 16; o > 0; o >>= 1) {
        s  += __shfl_xor_sync(0xffffffffu, s,  o);
        s2 += __shfl_xor_sync(0xffffffffu, s2, o);
    }
    int w = tid >> 5, lane = tid & 31;
    if (lane == 0) { sm1[w] = s; sm2v[w] = s2; }
    __syncthreads();
    if (tid == 0) {
        float ts = 0.f, ts2 = 0.f;
        #pragma unroll
        for (int i = 0; i < 8; i++) { ts += sm1[i]; ts2 += sm2v[i]; }
        float mean = ts / (float)DD;
        float var  = fmaxf((ts2 - (float)DD * mean * mean) / (float)(DD - 1), 0.f);
        stats[0] = mean; stats[1] = 1.f / (sqrtf(var) + 1e-8f);
    }
    __syncthreads();
    float mean = stats[0], rstd = stats[1];
    for (int i = tid; i < DD / 4; i += 256) {
        float4 v = *reinterpret_cast<const float4*>(rowbuf + i * 4);
        float o0 = (v.x - mean) * rstd * g[i * 4 + 0] + b[i * 4 + 0];
        float o1 = (v.y - mean) * rstd * g[i * 4 + 1] + b[i * 4 + 1];
        float o2 = (v.z - mean) * rstd * g[i * 4 + 2] + b[i * 4 + 2];
        float o3 = (v.w - mean) * rstd * g[i * 4 + 3] + b[i * 4 + 3];
        __half2* dst = reinterpret_cast<__half2*>(h2 + (size_t)row * DD + i * 4);
        dst[0] = __floats2half2_rn(o0, o1);
        dst[1] = __floats2half2_rn(o2, o3);
    }
}

// ---------------- split-K reduce (final, fp32 out) ----------------
__global__ void reduce2_kernel(const float* __restrict__ part, const float* __restrict__ bias,
                               const float* __restrict__ resid, float* __restrict__ out) {
    int i = blockIdx.x * 256 + threadIdx.x;
    const float4* p0 = reinterpret_cast<const float4*>(part);
    const float4* p1 = p0 + (TT * DD / 4);
    float4 a = p0[i], b = p1[i];
    int col = (i * 4) & (DD - 1);
    float4 bv = *reinterpret_cast<const float4*>(bias + col);
    float4 rv = reinterpret_cast<const float4*>(resid)[i];
    float4 o;
    o.x = a.x + b.x + bv.x + rv.x;
    o.y = a.y + b.y + bv.y + rv.y;
    o.z = a.z + b.z + bv.z + rv.z;
    o.w = a.w + b.w + bv.w + rv.w;
    reinterpret_cast<float4*>(out)[i] = o;
}

// ---------------- attention combine: merge NSPL KV-splits ----------------
__global__ void attn_combine(const float* __restrict__ part, const float* __restrict__ ml,
                             __half* __restrict__ ctx) {
    int row = blockIdx.x, tid = threadIdx.x;
    int col = tid * 4;
    int head = col >> 6;
    float mv[NSPL], lv[NSPL];
    float m = -INFINITY;
    #pragma unroll
    for (int z = 0; z < NSPL; z++) {
        const float* mp = ml + ((size_t)(z * TT + row) * HH + head) * 2;
        mv[z] = mp[0]; lv[z] = mp[1];
        m = fmaxf(m, mv[z]);
    }
    float lsum = 0.f;
    float a[NSPL];
    #pragma unroll
    for (int z = 0; z < NSPL; z++) {
        a[z] = ex2_fast(mv[z] - m);
        lsum += lv[z] * a[z];
    }
    float rl = 1.f / lsum;
    float v0 = 0.f, v1 = 0.f, v2 = 0.f, v3 = 0.f;
    #pragma unroll
    for (int z = 0; z < NSPL; z++) {
        float4 p = *reinterpret_cast<const float4*>(part + (size_t)z * TT * DD + (size_t)row * DD + col);
        v0 += p.x * a[z]; v1 += p.y * a[z]; v2 += p.z * a[z]; v3 += p.w * a[z];
    }
    __half2* dst = reinterpret_cast<__half2*>(ctx + (size_t)row * DD + col);
    dst[0] = __floats2half2_rn(v0 * rl, v1 * rl);
    dst[1] = __floats2half2_rn(v2 * rl, v3 * rl);
}

// ---------------- fp16 mma.sync GEMM (cp.async, BK=64, 2-stage, ldmatrix) ----------------
#define BM 128
#define BN 128
#define BK 64
#define LDS_ 72
#define GEMM_SMEM ((2 * BM * LDS_ + 2 * BN * LDS_) * 2)

template<bool GELU_, bool SPLIT, bool OUTH, bool QSC>
__global__ void __launch_bounds__(256, 2) mma_gemm(
    const __half* __restrict__ A, const __half* __restrict__ B0,
    const float* __restrict__ bias, const float* __restrict__ resid,
    void* Cv, int K, int lda, int ldb, int ldc)
{
    extern __shared__ __half hsm[];
    __half* Asm = hsm;
    __half* Bsm = hsm + 2 * BM * LDS_;

    if (SPLIT) {
        int z = blockIdx.z;
        A  += (size_t)z * K;
        B0 += (size_t)z * K;
        Cv = (void*)((float*)Cv + (size_t)z * TT * ldc);
    }

    int tid  = threadIdx.x;
    int warp = tid >> 5, lane = tid & 31;
    int wm = warp >> 2, wn = warp & 3;
    int g  = lane >> 2, tig = lane & 3;
    int lrow = lane & 15, lsel = lane >> 4;
    int rowBase = blockIdx.y * BM;
    int colBase = blockIdx.x * BN;
    int NC = K / BK;

    uint32_t abase = smem_u32(Asm);
    uint32_t bbase = smem_u32(Bsm);

    float acc[4][4][4];
    #pragma unroll
    for (int m = 0; m < 4; m++)
        #pragma unroll
        for (int n = 0; n < 4; n++)
            #pragma unroll
            for (int i = 0; i < 4; i++) acc[m][n][i] = 0.f;

    auto load_stage = [&](int c, int buf) {
        int k0 = c * BK;
        #pragma unroll
        for (int j = 0; j < 4; j++) {
            int f4 = j * 256 + tid;
            int r = f4 >> 3, cc = (f4 & 7) * 8;
            cp_async16(abase + (uint32_t)(buf * BM * LDS_ + r * LDS_ + cc) * 2,
                       A + (size_t)(rowBase + r) * lda + k0 + cc);
        }
        #pragma unroll
        for (int j = 0; j < 4; j++) {
            int f4 = j * 256 + tid;
            int r = f4 >> 3, cc = (f4 & 7) * 8;
            cp_async16(bbase + (uint32_t)(buf * BN * LDS_ + r * LDS_ + cc) * 2,
                       B0 + (size_t)(colBase + r) * ldb + k0 + cc);
        }
        CP_COMMIT();
    };

    auto compute = [&](int buf) {
        uint32_t As2 = abase + (uint32_t)(buf * BM * LDS_) * 2;
        uint32_t Bs2 = bbase + (uint32_t)(buf * BN * LDS_) * 2;
        #pragma unroll
        for (int kk = 0; kk < BK; kk += 16) {
            uint32_t af[4][4], bf[4][2];
            #pragma unroll
            for (int m = 0; m < 4; m++) {
                uint32_t a = As2 + (uint32_t)((wm * 64 + m * 16 + lrow) * LDS_ + kk + lsel * 8) * 2;
                ldsm_x4(af[m][0], af[m][1], af[m][2], af[m][3], a);
            }
            #pragma unroll
            for (int p = 0; p < 2; p++) {
                uint32_t a = Bs2 + (uint32_t)((wn * 32 + p * 16 + lrow) * LDS_ + kk + lsel * 8) * 2;
                ldsm_x4(bf[2 * p][0], bf[2 * p + 1][0], bf[2 * p][1], bf[2 * p + 1][1], a);
            }
            #pragma unroll
            for (int m = 0; m < 4; m++)
                #pragma unroll
                for (int n = 0; n < 4; n++)
                    mma_f16(acc[m][n], af[m], bf[n]);
        }
    };

    load_stage(0, 0);
    load_stage(1, 1);
    for (int c = 0; c < NC; c++) {
        if (c < NC - 1) { CP_WAIT1(); } else { CP_WAIT0(); }
        __syncthreads();
        compute(c & 1);
        __syncthreads();
        if (c + 2 <= NC - 1) load_stage(c + 2, c & 1);
    }

    const float SC = 0.18033688011112042f;  // 0.125 * log2(e)
    #pragma unroll
    for (int m = 0; m < 4; m++) {
        int r0 = rowBase + wm * 64 + m * 16 + g;
        #pragma unroll
        for (int n = 0; n < 4; n++) {
            int c0 = colBase + wn * 32 + n * 8 + tig * 2;
            #pragma unroll
            for (int half_ = 0; half_ < 2; half_++) {
                int r = r0 + half_ * 8;
                float v0 = acc[m][n][half_ * 2 + 0];
                float v1 = acc[m][n][half_ * 2 + 1];
                if (bias) { v0 += __ldg(bias + c0); v1 += __ldg(bias + c0 + 1); }
                if (GELU_) { v0 = gelu_f(v0); v1 = gelu_f(v1); }
                if (resid) {
                    float2 rv = *reinterpret_cast<const float2*>(resid + (size_t)r * ldc + c0);
                    v0 += rv.x; v1 += rv.y;
                }
                if (OUTH) {
                    if (QSC && colBase < 1024) { v0 *= SC; v1 *= SC; }
                    __half* Ch = (__half*)Cv + (size_t)r * ldc + c0;
                    *reinterpret_cast<__half2*>(Ch) = __floats2half2_rn(v0, v1);
                } else {
                    *reinterpret_cast<float2*>((float*)Cv + (size_t)r * ldc + c0) = make_float2(v0, v1);
                }
            }
        }
    }
}

// ---------------- fp16 causal flash attention, KV-split=NSPL, partial outputs ----------------
#define QLD 72
#define KLD 72
#define VLD 72
#define AOFF_K (128 * QLD)
#define AOFF_V (AOFF_K + 2 * 64 * KLD)
#define ATT_SMEM ((AOFF_V + 2 * 64 * VLD) * 2)

__global__ void __launch_bounds__(256, 2) attn_mma(const __half* __restrict__ QKVp,
                                                   float* __restrict__ part,
                                                   float* __restrict__ ml) {
    extern __shared__ __half smh[];
    __half* Qs = smh;            // 128 x QLD, reused as Ps
    __half* Ps = Qs;

    int qt = gridDim.x - 1 - blockIdx.x;
    int head = blockIdx.y;
    int z = blockIdx.z;
    int tid = threadIdx.x, warp = tid >> 5, lane = tid & 31;
    int g = lane >> 2, tig = lane & 3;
    int lrow = lane & 15, lsel = lane >> 4;
    int m0 = warp * 16;
    int base = qt * 128;

    int ntiles = ((base + 127) >> 6) + 1;
    int chunk = (ntiles + NSPL - 1) / NSPL;
    int t0 = z * chunk; if (t0 > ntiles) t0 = ntiles;
    int t1 = t0 + chunk; if (t1 > ntiles) t1 = ntiles;

    const __half* Qg = QKVp + (size_t)base * NQKV + head * 64;
    const __half* Kg = QKVp + 1024 + head * 64;
    const __half* Vg = QKVp + 2048 + head * 64;

    uint32_t qaddr = smem_u32(smh);
    uint32_t kaddr = smem_u32(smh + AOFF_K);
    uint32_t vaddr = smem_u32(smh + AOFF_V);

    auto load_tile = [&](int kt, int b) {
        const __half* Ksrc = Kg + (size_t)(kt * 64) * NQKV;
        const __half* Vsrc = Vg + (size_t)(kt * 64) * NQKV;
        uint32_t kb = kaddr + (uint32_t)(b * 64 * KLD) * 2;
        uint32_t vb = vaddr + (uint32_t)(b * 64 * VLD) * 2;
        #pragma unroll
        for (int j = 0; j < 2; j++) {
            int c = j * 256 + tid;
            int r = c >> 3, o = (c & 7) * 8;
            cp_async16(kb + (uint32_t)(r * KLD + o) * 2, Ksrc + (size_t)r * NQKV + o);
            cp_async16(vb + (uint32_t)(r * VLD + o) * 2, Vsrc + (size_t)r * NQKV + o);
        }
        CP_COMMIT();
    };

    #pragma unroll
    for (int j = 0; j < 4; j++) {
        int c = j * 256 + tid;
        int r = c >> 3, o = (c & 7) * 8;
        cp_async16(qaddr + (uint32_t)(r * QLD + o) * 2, Qg + (size_t)r * NQKV + o);
    }
    CP_COMMIT();
    if (t0 < t1)     load_tile(t0, 0);
    if (t0 + 1 < t1) load_tile(t0 + 1, 1);

    if (t0 + 1 < t1)      { CP_WAIT2(); }
    else if (t0 < t1)     { CP_WAIT1(); }
    else                  { CP_WAIT0(); }
    __syncthreads();

    uint32_t qf[4][4];
    #pragma unroll
    for (int kc = 0; kc < 4; kc++) {
        uint32_t a = qaddr + (uint32_t)((m0 + lrow) * QLD + kc * 16 + lsel * 8) * 2;
        ldsm_x4(qf[kc][0], qf[kc][1], qf[kc][2], qf[kc][3], a);
    }
    __syncthreads();     // qf extracted before Ps overwrites Qs

    float mrow0 = -INFINITY, mrow1 = -INFINITY, lrow0v = 0.f, lrow1v = 0.f;
    float o[8][4];
    #pragma unroll
    for (int n = 0; n < 8; n++)
        #pragma unroll
        for (int i = 0; i < 4; i++) o[n][i] = 0.f;

    int q0 = base + m0 + g, q1 = q0 + 8;
    int qwmin = base + m0;
    int qwmax = base + m0 + 15;
    uint32_t lm_off = ((uint32_t)((lane & 15) * VLD + ((lane >> 4) & 1) * 8)) * 2;

    for (int kt = t0; kt < t1; kt++) {
        int cur = (kt - t0) & 1;
        if (kt < t1 - 1) { CP_WAIT1(); } else { CP_WAIT0(); }
        __syncthreads();

        uint32_t ktile = kaddr + (uint32_t)(cur * 64 * KLD) * 2;
        uint32_t vtile = vaddr + (uint32_t)(cur * 64 * VLD) * 2;

        if (kt * 64 <= qwmax) {
            float s[8][4];
            #pragma unroll
            for (int n = 0; n < 8; n++)
                #pragma unroll
                for (int i = 0; i < 4; i++) s[n][i] = 0.f;
            #pragma unroll
            for (int kc = 0; kc < 4; kc++) {
                uint32_t bf[8][2];
                #pragma unroll
                for (int p = 0; p < 4; p++) {
                    uint32_t a = ktile + (uint32_t)((p * 16 + lrow) * KLD + kc * 16 + lsel * 8) * 2;
                    ldsm_x4(bf[2 * p][0], bf[2 * p + 1][0], bf[2 * p][1], bf[2 * p + 1][1], a);
                }
                #pragma unroll
                for (int n = 0; n < 8; n++)
                    mma_f16(s[n], qf[kc], bf[n]);
            }

            if (kt * 64 + 63 > qwmin) {
                #pragma unroll
                for (int n = 0; n < 8; n++) {
                    int k0 = kt * 64 + n * 8 + tig * 2;
                    if (k0     > q0) s[n][0] = -INFINITY;
                    if (k0 + 1 > q0) s[n][1] = -INFINITY;
                    if (k0     > q1) s[n][2] = -INFINITY;
                    if (k0 + 1 > q1) s[n][3] = -INFINITY;
                }
            }

            float mx0 = -INFINITY, mx1 = -INFINITY;
            #pragma unroll
            for (int n = 0; n < 8; n++) {
                mx0 = fmaxf(mx0, fmaxf(s[n][0], s[n][1]));
                mx1 = fmaxf(mx1, fmaxf(s[n][2], s[n][3]));
            }
            mx0 = fmaxf(mx0, __shfl_xor_sync(0xffffffffu, mx0, 1));
            mx0 = fmaxf(mx0, __shfl_xor_sync(0xffffffffu, mx0, 2));
            mx1 = fmaxf(mx1, __shfl_xor_sync(0xffffffffu, mx1, 1));
            mx1 = fmaxf(mx1, __shfl_xor_sync(0xffffffffu, mx1, 2));
            float mn0 = fmaxf(mrow0, mx0), mn1 = fmaxf(mrow1, mx1);
            float sc0 = ex2_fast(mrow0 - mn0), sc1 = ex2_fast(mrow1 - mn1);
            mrow0 = mn0; mrow1 = mn1;

            float ps0 = 0.f, ps1 = 0.f;
            #pragma unroll
            for (int n = 0; n < 8; n++) {
                float p0 = ex2_fast(s[n][0] - mn0);
                float p1 = ex2_fast(s[n][1] - mn0);
                float p2 = ex2_fast(s[n][2] - mn1);
                float p3 = ex2_fast(s[n][3] - mn1);
                ps0 += p0 + p1; ps1 += p2 + p3;
                *reinterpret_cast<__half2*>(&Ps[(m0 + g    ) * QLD + n * 8 + tig * 2]) =
                    __floats2half2_rn(p0, p1);
                *reinterpret_cast<__half2*>(&Ps[(m0 + g + 8) * QLD + n * 8 + tig * 2]) =
                    __floats2half2_rn(p2, p3);
            }
            ps0 += __shfl_xor_sync(0xffffffffu, ps0, 1);
            ps0 += __shfl_xor_sync(0xffffffffu, ps0, 2);
            ps1 += __shfl_xor_sync(0xffffffffu, ps1, 1);
            ps1 += __shfl_xor_sync(0xffffffffu, ps1, 2);
            lrow0v = lrow0v * sc0 + ps0;
            lrow1v = lrow1v * sc1 + ps1;

            #pragma unroll
            for (int n = 0; n < 8; n++) {
                o[n][0] *= sc0; o[n][1] *= sc0; o[n][2] *= sc1; o[n][3] *= sc1;
            }
            __syncwarp();

            #pragma unroll
            for (int kc = 0; kc < 4; kc++) {
                uint32_t pf[4];
                uint32_t pa = qaddr + (uint32_t)((m0 + lrow) * QLD + kc * 16 + lsel * 8) * 2;
                ldsm_x4(pf[0], pf[1], pf[2], pf[3], pa);
                #pragma unroll
                for (int nb = 0; nb < 4; nb++) {
                    uint32_t v0, v1, v2, v3;
                    uint32_t a = vtile + lm_off + (uint32_t)(kc * 16 * VLD + nb * 16) * 2;
                    asm volatile(
                        "ldmatrix.sync.aligned.m8n8.x4.trans.shared.b16 {%0,%1,%2,%3}, [%4];"
                        : "=r"(v0), "=r"(v1), "=r"(v2), "=r"(v3) : "r"(a));
                    uint32_t vfA[2] = {v0, v1};
                    uint32_t vfB[2] = {v2, v3};
                    mma_f16(o[nb * 2    ], pf, vfA);
                    mma_f16(o[nb * 2 + 1], pf, vfB);
                }
            }
        }
        __syncthreads();
        if (kt + 2 < t1) load_tile(kt + 2, cur);
    }

    // write unnormalized partials + (m, l)
    float* po = part + (size_t)z * TT * DD;
    if (tig == 0) {
        float* mp0 = ml + ((size_t)(z * TT + q0) * HH + head) * 2;
        float* mp1 = ml + ((size_t)(z * TT + q1) * HH + head) * 2;
        mp0[0] = mrow0; mp0[1] = lrow0v;
        mp1[0] = mrow1; mp1[1] = lrow1v;
    }
    float* out0 = po + (size_t)q0 * DD + head * 64;
    float* out1 = po + (size_t)q1 * DD + head * 64;
    #pragma unroll
    for (int n = 0; n < 8; n++) {
        int c = n * 8 + tig * 2;
        *reinterpret_cast<float2*>(out0 + c) = make_float2(o[n][0], o[n][1]);
        *reinterpret_cast<float2*>(out1 + c) = make_float2(o[n][2], o[n][3]);
    }
}

// ---------------- launch ----------------
extern "C" void kernel_launch(void* const* d_in, const int* in_sizes, int n_in,
                              void* d_out, int out_size) {
    const float* x     = (const float*)d_in[0];
    const float* wq    = (const float*)d_in[1];
    const float* wk    = (const float*)d_in[2];
    const float* wv    = (const float*)d_in[3];
    const float* wo    = (const float*)d_in[4];
    const float* bo    = (const float*)d_in[5];
    const float* ln1_g = (const float*)d_in[6];
    const float* ln1_b = (const float*)d_in[7];
    const float* ln2_g = (const float*)d_in[8];
    const float* ln2_b = (const float*)d_in[9];
    const float* w1    = (const float*)d_in[10];
    const float* b1    = (const float*)d_in[11];
    const float* w2    = (const float*)d_in[12];
    const float* b2    = (const float*)d_in[13];
    float* out = (float*)d_out;

    __half *h1, *qkv, *ctx, *h2, *ffn, *wt;
    float *x2, *part, *ml;
    cudaGetSymbolAddress((void**)&h1,   g_h1);
    cudaGetSymbolAddress((void**)&qkv,  g_qkv);
    cudaGetSymbolAddress((void**)&ctx,  g_ctx);
    cudaGetSymbolAddress((void**)&x2,   g_x2);
    cudaGetSymbolAddress((void**)&h2,   g_h2);
    cudaGetSymbolAddress((void**)&ffn,  g_ffn);
    cudaGetSymbolAddress((void**)&part, g_part);
    cudaGetSymbolAddress((void**)&ml,   g_ml);
    cudaGetSymbolAddress((void**)&wt,   g_wt);

    const int M1 = 1024 * 1024;
    const __half* wt_qkv = wt;
    const __half* wt_o   = wt + 3 * M1;
    const __half* wt_1   = wt + 4 * M1;
    const __half* wt_2   = wt + 8 * M1;

    cudaFuncSetAttribute(attn_mma, cudaFuncAttributeMaxDynamicSharedMemorySize, ATT_SMEM);
    cudaFuncSetAttribute(mma_gemm<false, false, true,  true >, cudaFuncAttributeMaxDynamicSharedMemorySize, GEMM_SMEM);
    cudaFuncSetAttribute(mma_gemm<false, true,  false, false>, cudaFuncAttributeMaxDynamicSharedMemorySize, GEMM_SMEM);
    cudaFuncSetAttribute(mma_gemm<true,  false, true,  false>, cudaFuncAttributeMaxDynamicSharedMemorySize, GEMM_SMEM);

    // wtrans (#1), LN1 (#2), QKV (#3), attention (#4 — profiled)
    wtrans_kernel<<<12288, 256>>>(wq, wk, wv, wo, w1, w2, wt);
    ln_kernel<<<TT, 256>>>(x, ln1_g, ln1_b, h1);
    mma_gemm<false, false, true, true><<<dim3(NQKV / BN, TT / BM), 256, GEMM_SMEM>>>(
        h1, wt_qkv, nullptr, nullptr, qkv, DD, DD, DD, NQKV);
    attn_mma<<<dim3(TT / 128, HH, NSPL), 256, ATT_SMEM>>>(qkv, part, ml);
    attn_combine<<<TT, 256>>>(part, ml, ctx);
    mma_gemm<false, true, false, false><<<dim3(DD / BN, TT / BM, 2), 256, GEMM_SMEM>>>(
        ctx, wt_o, nullptr, nullptr, part, DD / 2, DD, DD, DD);
    reduce_ln<<<TT, 256>>>(part, bo, x, ln2_g, ln2_b, x2, h2);
    mma_gemm<true, false, true, false><<<dim3(DFF / BN, TT / BM), 256, GEMM_SMEM>>>(
        h2, wt_1, b1, nullptr, ffn, DD, DD, DD, DFF);
    mma_gemm<false, true, false, false><<<dim3(DD / BN, TT / BM, 2), 256, GEMM_SMEM>>>(
        ffn, wt_2, nullptr, nullptr, part, DFF / 2, DFF, DFF, DD);
    reduce2_kernel<<<TT * DD / 4 / 256, 256>>>(part, b2, x2, out);
}